// round 6
// baseline (speedup 1.0000x reference)
#include <cuda_runtime.h>
#include <math.h>

#define NB   8
#define NH   16
#define LQ   128
#define LC   4096
#define DD   1024
#define HL   (NH * LQ)   // 2048
#define TOPK 5
#define EPS  1e-8f

#define ATTN_BLOCKS_PER_B 128
#define QV_BLOCKS_PER_B   8
#define BLOCKS_PER_B      (ATTN_BLOCKS_PER_B + QV_BLOCKS_PER_B)   // 136

// Scratch (__device__ globals; zero-initialized at load; every consumer
// resets what it read, so graph replays are self-consistent).
__device__ float g_avg[NB * LC];
__device__ float g_qvec[NB * DD];
__device__ int   g_cnt[NB];
__device__ float g_loss_sum;
__device__ int   g_done;

// ---------------------------------------------------------------------------
// helpers
// ---------------------------------------------------------------------------
__device__ __forceinline__ float warp_sum(float v) {
    #pragma unroll
    for (int off = 16; off > 0; off >>= 1)
        v += __shfl_down_sync(0xffffffffu, v, off);
    return v;
}
__device__ __forceinline__ unsigned long long warp_max64(unsigned long long k) {
    #pragma unroll
    for (int off = 16; off > 0; off >>= 1) {
        unsigned long long o = __shfl_down_sync(0xffffffffu, k, off);
        if (o > k) k = o;
    }
    return k;
}
// orderable mapping: preserves float total order as unsigned compare
__device__ __forceinline__ unsigned ord(float f) {
    unsigned fb = __float_as_uint(f);
    unsigned m  = (unsigned)((int)fb >> 31);
    return fb ^ (m | 0x80000000u);
}

// ---------------------------------------------------------------------------
// tail: per-batch top-5 (min-index tie-break = jax top_k) + cosine vs mean
// question vector; folds into global mean; resets scratch for next replay.
// Runs inside the last-arriving block of each batch (256 threads).
// Register pressure deliberately modest: kernel is capped at 32 regs so the
// 1088 streaming blocks keep 8 blocks/SM; spills here are fine (8 blocks).
// ---------------------------------------------------------------------------
__device__ void tail_for_batch(int b, const float* __restrict__ ctx,
                               float* __restrict__ out) {
    __shared__ float              s_attn[LC];     // 16 KB
    __shared__ float              s_q[DD];        // 4 KB
    __shared__ float              s_wv[8];
    __shared__ unsigned long long s_key[8];
    __shared__ int                s_top[TOPK];
    __shared__ float              s_red[2 * TOPK][8];

    const int tid  = threadIdx.x;
    const int lane = tid & 31;
    const int wid  = tid >> 5;
    const float4 zero4 = make_float4(0.f, 0.f, 0.f, 0.f);

    // mean question vector (thread t owns dims 4t..4t+3) -> smem
    {
        float4 q4 = reinterpret_cast<const float4*>(g_qvec)[b * (DD / 4) + tid];
        const float inv = 1.0f / (float)LQ;
        q4.x *= inv; q4.y *= inv; q4.z *= inv; q4.w *= inv;
        reinterpret_cast<float4*>(s_q)[tid] = q4;
        float p = warp_sum(q4.x * q4.x + q4.y * q4.y + q4.z * q4.z + q4.w * q4.w);
        if (lane == 0) s_wv[wid] = p;
    }

    // stage avg_attn into smem, then reset scratch for the next replay
    #pragma unroll
    for (int j = 0; j < 4; j++) {
        float4 v = reinterpret_cast<const float4*>(g_avg)[b * (LC / 4) + tid + j * 256];
        reinterpret_cast<float4*>(s_attn)[tid + j * 256] = v;
    }
    __syncthreads();
    #pragma unroll
    for (int j = 0; j < 4; j++)
        reinterpret_cast<float4*>(g_avg)[b * (LC / 4) + tid + j * 256] = zero4;
    reinterpret_cast<float4*>(g_qvec)[b * (DD / 4) + tid] = zero4;

    float qn = 0.0f;
    if (wid == 0) {
        float v = (lane < 8) ? s_wv[lane] : 0.0f;
        v = warp_sum(v);
        if (lane == 0) qn = fmaxf(sqrtf(v), EPS);
    }

    // 5 argmax rounds: packed (value, LC-1-i) keys, 64-bit max reduce
    for (int k = 0; k < TOPK; k++) {
        unsigned long long best = 0ull;
        #pragma unroll
        for (int j = 0; j < 16; j++) {
            int i = tid + j * 256;
            unsigned long long key =
                ((unsigned long long)ord(s_attn[i]) << 32) | (unsigned)(LC - 1 - i);
            if (key > best) best = key;
        }
        best = warp_max64(best);
        if (lane == 0) s_key[wid] = best;
        __syncthreads();
        if (wid == 0) {
            unsigned long long v = (lane < 8) ? s_key[lane] : 0ull;
            v = warp_max64(v);
            if (lane == 0) {
                int i = LC - 1 - (int)(unsigned)(v & 0xffffffffu);
                s_top[k] = i;
                s_attn[i] = -1.0f;   // below any real value under ord()
            }
        }
        __syncthreads();
    }

    // gather + reduce the 5 context rows (q read back from smem each k to
    // keep live registers low)
    {
        const float4 qq = reinterpret_cast<const float4*>(s_q)[tid];
        #pragma unroll
        for (int k = 0; k < TOPK; k++) {
            float4 cv = reinterpret_cast<const float4*>(ctx)
                        [((size_t)b * LC + (size_t)s_top[k]) * (DD / 4) + tid];
            float d = warp_sum(cv.x * qq.x + cv.y * qq.y +
                               cv.z * qq.z + cv.w * qq.w);
            float n = warp_sum(cv.x * cv.x + cv.y * cv.y +
                               cv.z * cv.z + cv.w * cv.w);
            if (lane == 0) { s_red[k][wid] = d; s_red[TOPK + k][wid] = n; }
        }
    }
    __syncthreads();

    if (wid == 0) {
        float loss = 0.0f;
        #pragma unroll
        for (int k = 0; k < TOPK; k++) {
            float dd = warp_sum((lane < 8) ? s_red[k][lane] : 0.0f);
            float nn = warp_sum((lane < 8) ? s_red[TOPK + k][lane] : 0.0f);
            if (lane == 0)
                loss += 1.0f - dd / (qn * fmaxf(sqrtf(nn), EPS));
        }
        if (lane == 0) {
            g_cnt[b] = 0;                      // reset batch ticket
            atomicAdd(&g_loss_sum, loss);
            __threadfence();
            int t = atomicAdd(&g_done, 1);
            if (t == NB - 1) {
                __threadfence();
                float total = atomicAdd(&g_loss_sum, 0.0f);  // coherent read
                out[0] = total / (float)(NB * TOPK);
                g_loss_sum = 0.0f;             // reset for next replay
                g_done     = 0;
            }
        }
    }
}

// ---------------------------------------------------------------------------
// One persistent kernel: 1088 producer blocks (128 attn + 8 qvec per batch);
// the 136th finisher of each batch runs that batch's tail inline.
// __launch_bounds__(256, 8): cap at 32 regs so the streaming wave keeps
// 8 blocks/SM (the R5 regression was reg-limited occupancy at 40 regs).
// ---------------------------------------------------------------------------
__global__ void __launch_bounds__(256, 8)
fused_all(const float4* __restrict__ w, const float4* __restrict__ q,
          const float* __restrict__ ctx, float* __restrict__ out) {
    const int id = blockIdx.x;
    int b;

    if (id < NB * ATTN_BLOCKS_PER_B) {     // ---- attn part (256 MB read) ----
        b = id >> 7;
        const int rem    = id & 127;
        const int seg    = rem >> 2;       // 0..31
        const int cchunk = rem & 3;        // 0..3
        const int lc4    = cchunk * 256 + threadIdx.x;
        const int ROWS   = HL / 32;        // 64

        float4 acc = make_float4(0.f, 0.f, 0.f, 0.f);
        size_t base = ((size_t)b * HL + (size_t)seg * ROWS) * (LC / 4) + lc4;

        #pragma unroll 8
        for (int r = 0; r < ROWS; r++) {
            float4 v = w[base + (size_t)r * (LC / 4)];
            acc.x += v.x; acc.y += v.y; acc.z += v.z; acc.w += v.w;
        }
        float* dst = &g_avg[b * LC + lc4 * 4];
        atomicAdd(dst + 0, acc.x);
        atomicAdd(dst + 1, acc.y);
        atomicAdd(dst + 2, acc.z);
        atomicAdd(dst + 3, acc.w);
    } else {                               // ---- question part (4 MB) ----
        const int id2 = id - NB * ATTN_BLOCKS_PER_B;
        b = id2 >> 3;
        const int seg = id2 & 7;           // 16 lq rows each
        const int tid = threadIdx.x;

        float4 acc = make_float4(0.f, 0.f, 0.f, 0.f);
        size_t base = ((size_t)b * LQ + (size_t)seg * 16) * (DD / 4) + tid;

        #pragma unroll
        for (int r = 0; r < 16; r++) {
            float4 v = q[base + (size_t)r * (DD / 4)];
            acc.x += v.x; acc.y += v.y; acc.z += v.z; acc.w += v.w;
        }
        float* dst = &g_qvec[b * DD + tid * 4];
        atomicAdd(dst + 0, acc.x);
        atomicAdd(dst + 1, acc.y);
        atomicAdd(dst + 2, acc.z);
        atomicAdd(dst + 3, acc.w);
    }

    // ---- per-batch ticket; last finisher runs the tail -------------------
    __threadfence();
    __syncthreads();
    __shared__ int s_ticket;
    if (threadIdx.x == 0)
        s_ticket = atomicAdd(&g_cnt[b], 1);
    __syncthreads();

    if (s_ticket == BLOCKS_PER_B - 1) {
        __threadfence();                   // acquire: see all producers' sums
        tail_for_batch(b, ctx, out);
    }
}

// ---------------------------------------------------------------------------
extern "C" void kernel_launch(void* const* d_in, const int* in_sizes, int n_in,
                              void* d_out, int out_size) {
    const float* q   = (const float*)d_in[0];  // question_emb  [8,128,1024]
    const float* ctx = (const float*)d_in[1];  // context_emb   [8,4096,1024]
    const float* w   = (const float*)d_in[2];  // cross_attn    [8,16,128,4096]

    fused_all<<<NB * BLOCKS_PER_B, 256>>>((const float4*)w, (const float4*)q,
                                          ctx, (float*)d_out);
}

// round 7
// speedup vs baseline: 1.1200x; 1.1200x over previous
#include <cuda_runtime.h>
#include <math.h>

#define NB   8
#define NH   16
#define LQ   128
#define LC   4096
#define DD   1024
#define HL   (NH * LQ)   // 2048
#define TOPK 5
#define EPS  1e-8f

// 64 attn blocks per batch (16 row-segs x 4 col-chunks, 128 rows each)
// + 8 qvec blocks per batch. 8*(64+8) = 576 total blocks:
// single wave even at 4 blocks/SM (592 slots), so register count is free
// to grow for load-pipeline MLP (the R5 two-wave / R6 reg-cap failures).
#define ATTN_BLOCKS_PER_B 64
#define QV_BLOCKS_PER_B   8
#define BLOCKS_PER_B      (ATTN_BLOCKS_PER_B + QV_BLOCKS_PER_B)   // 72
#define ATTN_ROWS         (HL / 16)                               // 128

// Scratch (__device__ globals; zero-initialized at load; every consumer
// resets what it read, so graph replays are self-consistent).
__device__ float g_avg[NB * LC];
__device__ float g_qvec[NB * DD];
__device__ int   g_cnt[NB];
__device__ float g_loss_sum;
__device__ int   g_done;

// ---------------------------------------------------------------------------
// helpers
// ---------------------------------------------------------------------------
__device__ __forceinline__ float warp_sum(float v) {
    #pragma unroll
    for (int off = 16; off > 0; off >>= 1)
        v += __shfl_down_sync(0xffffffffu, v, off);
    return v;
}
__device__ __forceinline__ unsigned long long warp_max64(unsigned long long k) {
    #pragma unroll
    for (int off = 16; off > 0; off >>= 1) {
        unsigned long long o = __shfl_down_sync(0xffffffffu, k, off);
        if (o > k) k = o;
    }
    return k;
}
// orderable mapping: preserves float total order as unsigned compare
__device__ __forceinline__ unsigned ord(float f) {
    unsigned fb = __float_as_uint(f);
    unsigned m  = (unsigned)((int)fb >> 31);
    return fb ^ (m | 0x80000000u);
}

// ---------------------------------------------------------------------------
// tail: per-batch top-5 (min-index tie-break = jax top_k) + cosine vs mean
// question vector; folds into global mean; resets scratch for next replay.
// Runs inside the last-arriving block of each batch (256 threads).
// ---------------------------------------------------------------------------
__device__ void tail_for_batch(int b, const float* __restrict__ ctx,
                               float* __restrict__ out) {
    __shared__ float              s_attn[LC];     // 16 KB
    __shared__ float              s_q[DD];        // 4 KB
    __shared__ float              s_wv[8];
    __shared__ unsigned long long s_key[8];
    __shared__ int                s_top[TOPK];
    __shared__ float              s_red[2 * TOPK][8];

    const int tid  = threadIdx.x;
    const int lane = tid & 31;
    const int wid  = tid >> 5;
    const float4 zero4 = make_float4(0.f, 0.f, 0.f, 0.f);

    // mean question vector (thread t owns dims 4t..4t+3) -> smem
    {
        float4 q4 = reinterpret_cast<const float4*>(g_qvec)[b * (DD / 4) + tid];
        const float inv = 1.0f / (float)LQ;
        q4.x *= inv; q4.y *= inv; q4.z *= inv; q4.w *= inv;
        reinterpret_cast<float4*>(s_q)[tid] = q4;
        float p = warp_sum(q4.x * q4.x + q4.y * q4.y + q4.z * q4.z + q4.w * q4.w);
        if (lane == 0) s_wv[wid] = p;
    }

    // stage avg_attn into smem, then reset scratch for the next replay
    #pragma unroll
    for (int j = 0; j < 4; j++) {
        float4 v = reinterpret_cast<const float4*>(g_avg)[b * (LC / 4) + tid + j * 256];
        reinterpret_cast<float4*>(s_attn)[tid + j * 256] = v;
    }
    __syncthreads();
    #pragma unroll
    for (int j = 0; j < 4; j++)
        reinterpret_cast<float4*>(g_avg)[b * (LC / 4) + tid + j * 256] = zero4;
    reinterpret_cast<float4*>(g_qvec)[b * (DD / 4) + tid] = zero4;

    float qn = 0.0f;
    if (wid == 0) {
        float v = (lane < 8) ? s_wv[lane] : 0.0f;
        v = warp_sum(v);
        if (lane == 0) qn = fmaxf(sqrtf(v), EPS);
    }

    // 5 argmax rounds: packed (value, LC-1-i) keys, 64-bit max reduce
    for (int k = 0; k < TOPK; k++) {
        unsigned long long best = 0ull;
        #pragma unroll
        for (int j = 0; j < 16; j++) {
            int i = tid + j * 256;
            unsigned long long key =
                ((unsigned long long)ord(s_attn[i]) << 32) | (unsigned)(LC - 1 - i);
            if (key > best) best = key;
        }
        best = warp_max64(best);
        if (lane == 0) s_key[wid] = best;
        __syncthreads();
        if (wid == 0) {
            unsigned long long v = (lane < 8) ? s_key[lane] : 0ull;
            v = warp_max64(v);
            if (lane == 0) {
                int i = LC - 1 - (int)(unsigned)(v & 0xffffffffu);
                s_top[k] = i;
                s_attn[i] = -1.0f;   // below any real value under ord()
            }
        }
        __syncthreads();
    }

    // gather + reduce the 5 context rows
    {
        const float4 qq = reinterpret_cast<const float4*>(s_q)[tid];
        #pragma unroll
        for (int k = 0; k < TOPK; k++) {
            float4 cv = reinterpret_cast<const float4*>(ctx)
                        [((size_t)b * LC + (size_t)s_top[k]) * (DD / 4) + tid];
            float d = warp_sum(cv.x * qq.x + cv.y * qq.y +
                               cv.z * qq.z + cv.w * qq.w);
            float n = warp_sum(cv.x * cv.x + cv.y * cv.y +
                               cv.z * cv.z + cv.w * cv.w);
            if (lane == 0) { s_red[k][wid] = d; s_red[TOPK + k][wid] = n; }
        }
    }
    __syncthreads();

    if (wid == 0) {
        float loss = 0.0f;
        #pragma unroll
        for (int k = 0; k < TOPK; k++) {
            float dd = warp_sum((lane < 8) ? s_red[k][lane] : 0.0f);
            float nn = warp_sum((lane < 8) ? s_red[TOPK + k][lane] : 0.0f);
            if (lane == 0)
                loss += 1.0f - dd / (qn * fmaxf(sqrtf(nn), EPS));
        }
        if (lane == 0) {
            g_cnt[b] = 0;                      // reset batch ticket
            atomicAdd(&g_loss_sum, loss);
            __threadfence();
            int t = atomicAdd(&g_done, 1);
            if (t == NB - 1) {
                __threadfence();
                float total = atomicAdd(&g_loss_sum, 0.0f);  // coherent read
                out[0] = total / (float)(NB * TOPK);
                g_loss_sum = 0.0f;             // reset for next replay
                g_done     = 0;
            }
        }
    }
}

// ---------------------------------------------------------------------------
// One kernel, one wave: 576 producer blocks; last finisher per batch runs
// that batch's tail inline. No launch bounds: registers free for MLP.
// ---------------------------------------------------------------------------
__global__ void
fused_all(const float4* __restrict__ w, const float4* __restrict__ q,
          const float* __restrict__ ctx, float* __restrict__ out) {
    const int id = blockIdx.x;
    int b;

    if (id < NB * ATTN_BLOCKS_PER_B) {     // ---- attn part (256 MB read) ----
        b = id >> 6;                       // /64
        const int rem    = id & 63;
        const int seg    = rem >> 2;       // 0..15
        const int cchunk = rem & 3;        // 0..3
        const int lc4    = cchunk * 256 + threadIdx.x;

        float4 acc = make_float4(0.f, 0.f, 0.f, 0.f);
        size_t base = ((size_t)b * HL + (size_t)seg * ATTN_ROWS) * (LC / 4) + lc4;

        #pragma unroll 16
        for (int r = 0; r < ATTN_ROWS; r++) {
            float4 v = w[base + (size_t)r * (LC / 4)];
            acc.x += v.x; acc.y += v.y; acc.z += v.z; acc.w += v.w;
        }
        float* dst = &g_avg[b * LC + lc4 * 4];
        atomicAdd(dst + 0, acc.x);
        atomicAdd(dst + 1, acc.y);
        atomicAdd(dst + 2, acc.z);
        atomicAdd(dst + 3, acc.w);
    } else {                               // ---- question part (4 MB) ----
        const int id2 = id - NB * ATTN_BLOCKS_PER_B;
        b = id2 >> 3;
        const int seg = id2 & 7;           // 16 lq rows each
        const int tid = threadIdx.x;

        float4 acc = make_float4(0.f, 0.f, 0.f, 0.f);
        size_t base = ((size_t)b * LQ + (size_t)seg * 16) * (DD / 4) + tid;

        #pragma unroll
        for (int r = 0; r < 16; r++) {
            float4 v = q[base + (size_t)r * (DD / 4)];
            acc.x += v.x; acc.y += v.y; acc.z += v.z; acc.w += v.w;
        }
        float* dst = &g_qvec[b * DD + tid * 4];
        atomicAdd(dst + 0, acc.x);
        atomicAdd(dst + 1, acc.y);
        atomicAdd(dst + 2, acc.z);
        atomicAdd(dst + 3, acc.w);
    }

    // ---- per-batch ticket; last finisher runs the tail -------------------
    __threadfence();
    __syncthreads();
    __shared__ int s_ticket;
    if (threadIdx.x == 0)
        s_ticket = atomicAdd(&g_cnt[b], 1);
    __syncthreads();

    if (s_ticket == BLOCKS_PER_B - 1) {
        __threadfence();                   // acquire: see all producers' sums
        tail_for_batch(b, ctx, out);
    }
}

// ---------------------------------------------------------------------------
extern "C" void kernel_launch(void* const* d_in, const int* in_sizes, int n_in,
                              void* d_out, int out_size) {
    const float* q   = (const float*)d_in[0];  // question_emb  [8,128,1024]
    const float* ctx = (const float*)d_in[1];  // context_emb   [8,4096,1024]
    const float* w   = (const float*)d_in[2];  // cross_attn    [8,16,128,4096]

    fused_all<<<NB * BLOCKS_PER_B, 256>>>((const float4*)w, (const float4*)q,
                                          ctx, (float*)d_out);
}

// round 8
// speedup vs baseline: 1.1529x; 1.0294x over previous
#include <cuda_runtime.h>
#include <math.h>

#define NB   8
#define NH   16
#define LQ   128
#define LC   4096
#define DD   1024
#define HL   (NH * LQ)   // 2048
#define TOPK 5
#define EPS  1e-8f

// Scratch (__device__ globals; zero-initialized at load; consumers reset what
// they read, so graph replays are self-consistent with no zero kernel).
__device__ float g_avg[NB * LC];
__device__ float g_qvec[NB * DD];
__device__ float g_loss_sum;
__device__ int   g_done;

// ---------------------------------------------------------------------------
// helpers
// ---------------------------------------------------------------------------
__device__ __forceinline__ float warp_sum(float v) {
    #pragma unroll
    for (int off = 16; off > 0; off >>= 1)
        v += __shfl_down_sync(0xffffffffu, v, off);
    return v;
}
__device__ __forceinline__ unsigned long long warp_max64(unsigned long long k) {
    #pragma unroll
    for (int off = 16; off > 0; off >>= 1) {
        unsigned long long o = __shfl_down_sync(0xffffffffu, k, off);
        if (o > k) k = o;
    }
    return k;
}
// orderable mapping: preserves float total order as unsigned compare
__device__ __forceinline__ unsigned ord(float f) {
    unsigned fb = __float_as_uint(f);
    unsigned m  = (unsigned)((int)fb >> 31);
    return fb ^ (m | 0x80000000u);
}

// ---------------------------------------------------------------------------
// 1. Stream: blocks [0,1024) sum attn over (h,lq); blocks [1024,1088) sum
//    question over lq. Exact R4 configuration (proven ~6.1 TB/s).
// ---------------------------------------------------------------------------
__global__ void __launch_bounds__(256)
fused_reduce(const float4* __restrict__ w, const float4* __restrict__ q) {
    const int id = blockIdx.x;

    if (id < 1024) {                       // ---- attn part (256 MB read) ----
        const int b      = id >> 7;
        const int rem    = id & 127;
        const int seg    = rem >> 2;       // 0..31
        const int cchunk = rem & 3;        // 0..3
        const int lc4    = cchunk * 256 + threadIdx.x;
        const int ROWS   = HL / 32;        // 64

        float4 acc = make_float4(0.f, 0.f, 0.f, 0.f);
        size_t base = ((size_t)b * HL + (size_t)seg * ROWS) * (LC / 4) + lc4;

        #pragma unroll 16
        for (int r = 0; r < ROWS; r++) {
            float4 v = w[base + (size_t)r * (LC / 4)];
            acc.x += v.x; acc.y += v.y; acc.z += v.z; acc.w += v.w;
        }
        float* dst = &g_avg[b * LC + lc4 * 4];
        atomicAdd(dst + 0, acc.x);
        atomicAdd(dst + 1, acc.y);
        atomicAdd(dst + 2, acc.z);
        atomicAdd(dst + 3, acc.w);
    } else {                               // ---- question part (4 MB) ----
        const int id2 = id - 1024;
        const int b   = id2 >> 3;
        const int seg = id2 & 7;           // 16 lq rows each
        const int tid = threadIdx.x;

        float4 acc = make_float4(0.f, 0.f, 0.f, 0.f);
        size_t base = ((size_t)b * LQ + (size_t)seg * 16) * (DD / 4) + tid;

        #pragma unroll
        for (int r = 0; r < 16; r++) {
            float4 v = q[base + (size_t)r * (DD / 4)];
            acc.x += v.x; acc.y += v.y; acc.z += v.z; acc.w += v.w;
        }
        float* dst = &g_qvec[b * DD + tid * 4];
        atomicAdd(dst + 0, acc.x);
        atomicAdd(dst + 1, acc.y);
        atomicAdd(dst + 2, acc.z);
        atomicAdd(dst + 3, acc.w);
    }
}

// ---------------------------------------------------------------------------
// 2. Tail: per-batch top-5 (min-index tie-break = jax top_k) + cosine vs mean
//    question vector; global mean by ticket; resets scratch for next replay.
//    Latency-optimized: single-pass register top-5, batched ctx gather.
// grid: NB x 256 threads
// ---------------------------------------------------------------------------
__global__ void __launch_bounds__(256, 1)
tail_kernel(const float* __restrict__ ctx, float* __restrict__ out) {
    __shared__ float              s_wv[8];
    __shared__ unsigned long long s_key[8];
    __shared__ unsigned long long s_best;
    __shared__ int                s_top[TOPK];
    __shared__ float              s_red[2 * TOPK][8];

    const int b    = blockIdx.x;
    const int tid  = threadIdx.x;
    const int lane = tid & 31;
    const int wid  = tid >> 5;
    const float4 zero4 = make_float4(0.f, 0.f, 0.f, 0.f);

    // --- issue all g_avg loads first (4 independent LDG.128) --------------
    float4 av[4];
    #pragma unroll
    for (int j = 0; j < 4; j++)
        av[j] = reinterpret_cast<const float4*>(g_avg)[b * (LC / 4) + tid + j * 256];

    // --- mean question vector + norm partial (overlaps the loads above) ---
    float4 q4 = reinterpret_cast<const float4*>(g_qvec)[b * (DD / 4) + tid];
    const float inv = 1.0f / (float)LQ;
    q4.x *= inv; q4.y *= inv; q4.z *= inv; q4.w *= inv;
    {
        float p = warp_sum(q4.x * q4.x + q4.y * q4.y + q4.z * q4.z + q4.w * q4.w);
        if (lane == 0) s_wv[wid] = p;
    }
    reinterpret_cast<float4*>(g_qvec)[b * (DD / 4) + tid] = zero4;

    // --- single-pass local top-5: sorted-descending key list in registers --
    unsigned long long key[TOPK] = {0ull, 0ull, 0ull, 0ull, 0ull};
    #pragma unroll
    for (int j = 0; j < 4; j++) {
        const float vv[4] = {av[j].x, av[j].y, av[j].z, av[j].w};
        #pragma unroll
        for (int c = 0; c < 4; c++) {
            int idx = (tid + j * 256) * 4 + c;
            unsigned long long k =
                ((unsigned long long)ord(vv[c]) << 32) | (unsigned)(LC - 1 - idx);
            #pragma unroll
            for (int m = 0; m < TOPK; m++) {
                unsigned long long mx = (key[m] > k) ? key[m] : k;
                k      = (key[m] > k) ? k : key[m];
                key[m] = mx;
            }
        }
        // reset scratch for next replay
        reinterpret_cast<float4*>(g_avg)[b * (LC / 4) + tid + j * 256] = zero4;
    }

    // --- qnorm (warp0) ------------------------------------------------------
    float qn = 0.0f;
    if (wid == 0) {
        float v = (lane < 8) ? s_wv[lane] : 0.0f;
        v = warp_sum(v);
        if (lane == 0) qn = fmaxf(sqrtf(v), EPS);
    }

    // --- 5 extraction rounds over list heads only ---------------------------
    #pragma unroll
    for (int k = 0; k < TOPK; k++) {
        unsigned long long w = warp_max64(key[0]);
        if (lane == 0) s_key[wid] = w;
        __syncthreads();
        if (wid == 0) {
            unsigned long long v = (lane < 8) ? s_key[lane] : 0ull;
            v = warp_max64(v);
            if (lane == 0) {
                s_best  = v;
                s_top[k] = LC - 1 - (int)(unsigned)(v & 0xffffffffu);
            }
        }
        __syncthreads();
        // exactly one thread owns the winner (indices make keys unique): pop
        if (key[0] == s_best) {
            key[0] = key[1]; key[1] = key[2];
            key[2] = key[3]; key[3] = key[4]; key[4] = 0ull;
        }
    }

    // --- batched gather of all 5 context rows (one DRAM round-trip) ---------
    float4 cv[TOPK];
    #pragma unroll
    for (int k = 0; k < TOPK; k++)
        cv[k] = reinterpret_cast<const float4*>(ctx)
                    [((size_t)b * LC + (size_t)s_top[k]) * (DD / 4) + tid];

    // --- all 10 partial reductions, single barrier ---------------------------
    #pragma unroll
    for (int k = 0; k < TOPK; k++) {
        float d = warp_sum(cv[k].x * q4.x + cv[k].y * q4.y +
                           cv[k].z * q4.z + cv[k].w * q4.w);
        float n = warp_sum(cv[k].x * cv[k].x + cv[k].y * cv[k].y +
                           cv[k].z * cv[k].z + cv[k].w * cv[k].w);
        if (lane == 0) { s_red[k][wid] = d; s_red[TOPK + k][wid] = n; }
    }
    __syncthreads();

    if (wid == 0) {
        float loss = 0.0f;
        #pragma unroll
        for (int k = 0; k < TOPK; k++) {
            float dd = warp_sum((lane < 8) ? s_red[k][lane] : 0.0f);
            float nn = warp_sum((lane < 8) ? s_red[TOPK + k][lane] : 0.0f);
            if (lane == 0)
                loss += 1.0f - dd / (qn * fmaxf(sqrtf(nn), EPS));
        }
        if (lane == 0) {
            atomicAdd(&g_loss_sum, loss);
            __threadfence();
            int t = atomicAdd(&g_done, 1);
            if (t == NB - 1) {
                __threadfence();
                float total = atomicAdd(&g_loss_sum, 0.0f);  // coherent read
                out[0] = total / (float)(NB * TOPK);
                g_loss_sum = 0.0f;             // reset for next replay
                g_done     = 0;
            }
        }
    }
}

// ---------------------------------------------------------------------------
extern "C" void kernel_launch(void* const* d_in, const int* in_sizes, int n_in,
                              void* d_out, int out_size) {
    const float* q   = (const float*)d_in[0];  // question_emb  [8,128,1024]
    const float* ctx = (const float*)d_in[1];  // context_emb   [8,4096,1024]
    const float* w   = (const float*)d_in[2];  // cross_attn    [8,16,128,4096]

    fused_reduce<<<1024 + 64, 256>>>((const float4*)w, (const float4*)q);
    tail_kernel<<<NB, 256>>>(ctx, (float*)d_out);
}